// round 1
// baseline (speedup 1.0000x reference)
#include <cuda_runtime.h>
#include <math.h>

#define NN 50000
#define NC 10
#define NL 2
#define NE 800000
#define ND 128

// ---------------- scratch (device globals; no runtime allocation) ----------
__device__ float g_bufA[(size_t)NC * NN * ND];   // GCN output (attention input)
__device__ float g_bufB[(size_t)NC * NN * ND];   // attention output (layer 0)
__device__ float g_K[(size_t)NC * NN * ND];
__device__ float g_V[(size_t)NC * NN * ND];
__device__ float g_xw[(size_t)NC * NN * ND];     // X @ W for all classes
__device__ float g_oxw[(size_t)NN * ND];
__device__ float g_otmp[(size_t)NN * ND];
__device__ float g_ofe[(size_t)NN * ND];
__device__ float g_q[NC * ND];
__device__ float g_dinv[NC * NN];
__device__ int   g_cnt[NC * NN];
__device__ int   g_off[NC * NN];
__device__ int   g_cur[NC * NN];
__device__ int   g_csr[(size_t)NC * NE];
__device__ int   g_board[NN];

// ---------------- f32x2 helpers --------------------------------------------
__device__ __forceinline__ unsigned long long splat2(float a) {
    unsigned long long r;
    asm("mov.b64 %0, {%1, %1};" : "=l"(r) : "f"(a));
    return r;
}
__device__ __forceinline__ float2 ull2f2(unsigned long long u) {
    float2 f;
    asm("mov.b64 {%0, %1}, %2;" : "=f"(f.x), "=f"(f.y) : "l"(u));
    return f;
}
#define FMA2(d, a, b) asm("fma.rn.f32x2 %0, %1, %2, %0;" : "+l"(d) : "l"(a), "l"(b))

// ---------------- GEMM: C[M,128] = A[M,128] @ W[128,128] (+bias) -----------
// 256 threads, 128-row tile, W + A tile both smem-resident, 8x8 register tile
// accumulated as f32x2 pairs (packed FFMA2 -> 2x fp32 throughput).
#define GEMM_SMEM (2 * 128 * 132 * 4)

__global__ void __launch_bounds__(256) gemm128(const float* __restrict__ A,
                                               const float* __restrict__ W,
                                               const float* __restrict__ bias,
                                               float* __restrict__ Cmat, int M) {
    extern __shared__ float sm[];
    float* As = sm;              // [128][132] row-major (row, k)
    float* Ws = sm + 128 * 132;  // [128][132] row-major (k, j)

    const int tid  = threadIdx.x;
    const int row0 = blockIdx.x * 128;

#pragma unroll
    for (int it = 0; it < 16; ++it) {
        int idx = tid + it * 256;          // 0..4095 float4 slots
        int r   = idx >> 5;
        int k4  = idx & 31;
        float4 v = make_float4(0.f, 0.f, 0.f, 0.f);
        int gr = row0 + r;
        if (gr < M) v = *(const float4*)(A + (size_t)gr * 128 + k4 * 4);
        *(float4*)(As + r * 132 + k4 * 4) = v;
        float4 w = *(const float4*)(W + (size_t)idx * 4);
        *(float4*)(Ws + r * 132 + k4 * 4) = w;
    }
    __syncthreads();

    const int ty = tid >> 4, tx = tid & 15;
    const int i0 = ty * 8, j0 = tx * 8;

    unsigned long long acc[8][4];
#pragma unroll
    for (int r = 0; r < 8; ++r)
#pragma unroll
        for (int p = 0; p < 4; ++p) acc[r][p] = 0ULL;

#pragma unroll 4
    for (int k = 0; k < 128; ++k) {
        ulonglong2 bA = *(const ulonglong2*)(Ws + k * 132 + j0);
        ulonglong2 bB = *(const ulonglong2*)(Ws + k * 132 + j0 + 4);
#pragma unroll
        for (int r = 0; r < 8; ++r) {
            float av = As[(i0 + r) * 132 + k];
            unsigned long long a2 = splat2(av);
            FMA2(acc[r][0], a2, bA.x);
            FMA2(acc[r][1], a2, bA.y);
            FMA2(acc[r][2], a2, bB.x);
            FMA2(acc[r][3], a2, bB.y);
        }
    }

    float bj[8];
#pragma unroll
    for (int jj = 0; jj < 8; ++jj) bj[jj] = bias ? bias[j0 + jj] : 0.f;

#pragma unroll
    for (int r = 0; r < 8; ++r) {
        int gr = row0 + i0 + r;
        if (gr < M) {
            float2 f0 = ull2f2(acc[r][0]);
            float2 f1 = ull2f2(acc[r][1]);
            float2 f2 = ull2f2(acc[r][2]);
            float2 f3 = ull2f2(acc[r][3]);
            float4 o0 = make_float4(f0.x + bj[0], f0.y + bj[1], f1.x + bj[2], f1.y + bj[3]);
            float4 o1 = make_float4(f2.x + bj[4], f2.y + bj[5], f3.x + bj[6], f3.y + bj[7]);
            *(float4*)(Cmat + (size_t)gr * 128 + j0)     = o0;
            *(float4*)(Cmat + (size_t)gr * 128 + j0 + 4) = o1;
        }
    }
}

// ---------------- CSR construction -----------------------------------------
__global__ void zero_int(int* p, int n) {
    int i = blockIdx.x * blockDim.x + threadIdx.x;
    if (i < n) p[i] = 0;
}

__global__ void count_graph(const int* __restrict__ ge, int layer) {
    int i = blockIdx.x * blockDim.x + threadIdx.x;
    if (i >= NC * NE) return;
    int c = i / NE, e = i - c * NE;
    int dst = ge[(size_t)((c * NL + layer) * 2 + 1) * NE + e];
    atomicAdd(&g_cnt[c * NN + dst], 1);
}

__global__ void fill_graph(const int* __restrict__ ge, int layer) {
    int i = blockIdx.x * blockDim.x + threadIdx.x;
    if (i >= NC * NE) return;
    int c = i / NE, e = i - c * NE;
    int src = ge[(size_t)((c * NL + layer) * 2 + 0) * NE + e];
    int dst = ge[(size_t)((c * NL + layer) * 2 + 1) * NE + e];
    int pos = atomicAdd(&g_cur[c * NN + dst], 1);
    g_csr[(size_t)c * NE + pos] = src;
}

__global__ void count_ori(const int* __restrict__ oe, int layer) {
    int i = blockIdx.x * blockDim.x + threadIdx.x;
    if (i >= NE) return;
    int dst = oe[(size_t)(layer * 2 + 1) * NE + i];
    atomicAdd(&g_cnt[dst], 1);
}

__global__ void fill_ori(const int* __restrict__ oe, int layer) {
    int i = blockIdx.x * blockDim.x + threadIdx.x;
    if (i >= NE) return;
    int src = oe[(size_t)(layer * 2 + 0) * NE + i];
    int dst = oe[(size_t)(layer * 2 + 1) * NE + i];
    int pos = atomicAdd(&g_cur[dst], 1);
    g_csr[pos] = src;
}

// one block per class: exclusive scan of counts -> offsets/cursor, plus dinv
__global__ void scan_kernel() {
    __shared__ int part[1024];
    const int c = blockIdx.x, t = threadIdx.x;
    const int* cnt = g_cnt + c * NN;
    const int CH = (NN + 1023) / 1024;
    int s0 = t * CH;
    int s1 = s0 + CH; if (s1 > NN) s1 = NN;
    int sum = 0;
    for (int n = s0; n < s1; ++n) sum += cnt[n];
    part[t] = sum;
    __syncthreads();
    for (int d = 1; d < 1024; d <<= 1) {
        int v = (t >= d) ? part[t - d] : 0;
        __syncthreads();
        part[t] += v;
        __syncthreads();
    }
    int run = (t == 0) ? 0 : part[t - 1];
    for (int n = s0; n < s1; ++n) {
        int cv = cnt[n];
        g_off[c * NN + n]  = run;
        g_cur[c * NN + n]  = run;
        g_dinv[c * NN + n] = rsqrtf((float)(1 + cv));
        run += cv;
    }
}

// ---------------- GCN gather: out[n] = b + xw[n]*dinv[n]^2 + sum_in xw[s]*dinv[s]*dinv[n]
__global__ void __launch_bounds__(256) gather_kernel(const float* __restrict__ xw,
                                                     const float* __restrict__ bias,
                                                     float* __restrict__ out,
                                                     int numClasses) {
    int gw = blockIdx.x * 8 + (threadIdx.x >> 5);
    if (gw >= numClasses * NN) return;
    int lane = threadIdx.x & 31;
    int c = gw / NN;
    int n = gw - c * NN;
    const float* xwc = xw + (size_t)c * NN * 128;
    const int cn = c * NN + n;
    float dv = g_dinv[cn];
    float4 b4 = *(const float4*)(bias + lane * 4);
    float4 x4 = *(const float4*)(xwc + (size_t)n * 128 + lane * 4);
    float ws = dv * dv;
    float4 acc = make_float4(b4.x + x4.x * ws, b4.y + x4.y * ws,
                             b4.z + x4.z * ws, b4.w + x4.w * ws);
    int beg = g_off[cn];
    int end = beg + g_cnt[cn];
    const int* csr = g_csr + (size_t)c * NE;
    int j = beg;
    for (; j + 1 < end; j += 2) {
        int s0 = csr[j], s1 = csr[j + 1];
        float w0 = g_dinv[c * NN + s0] * dv;
        float w1 = g_dinv[c * NN + s1] * dv;
        float4 a0 = *(const float4*)(xwc + (size_t)s0 * 128 + lane * 4);
        float4 a1 = *(const float4*)(xwc + (size_t)s1 * 128 + lane * 4);
        acc.x += a0.x * w0 + a1.x * w1;
        acc.y += a0.y * w0 + a1.y * w1;
        acc.z += a0.z * w0 + a1.z * w1;
        acc.w += a0.w * w0 + a1.w * w1;
    }
    if (j < end) {
        int s0 = csr[j];
        float w0 = g_dinv[c * NN + s0] * dv;
        float4 a0 = *(const float4*)(xwc + (size_t)s0 * 128 + lane * 4);
        acc.x += a0.x * w0; acc.y += a0.y * w0;
        acc.z += a0.z * w0; acc.w += a0.w * w0;
    }
    *(float4*)(out + (size_t)cn * 128 + lane * 4) = acc;
}

// ---------------- q = label_emb @ Wq + bq ----------------------------------
__global__ void q_kernel(const float* __restrict__ label,
                         const float* __restrict__ Wq,
                         const float* __restrict__ bq) {
    __shared__ float Ls[NC * 128];
    int t = threadIdx.x;  // 128 threads
    for (int i = t; i < NC * 128; i += 128) Ls[i] = label[i];
    __syncthreads();
    for (int c = 0; c < NC; ++c) {
        float acc = bq[t];
#pragma unroll 8
        for (int h = 0; h < 128; ++h) acc += Ls[c * 128 + h] * Wq[h * 128 + t];
        g_q[c * 128 + t] = acc;
    }
}

// ---------------- attention: softmax(qK^T/sqrt(d)) V, per node -------------
__global__ void __launch_bounds__(128) attn_kernel(const float* __restrict__ K,
                                                   const float* __restrict__ V,
                                                   float* __restrict__ out,
                                                   int doRelu) {
    __shared__ float q_s[NC][128];
    __shared__ float s_s[4][NC][NC];
    int tid = threadIdx.x;
    for (int i = tid; i < NC * 128; i += 128) q_s[i >> 7][i & 127] = g_q[i];
    __syncthreads();
    int w = tid >> 5, lane = tid & 31;
    int n = blockIdx.x * 4 + w;
    if (n >= NN) return;

    float4 kr[NC];
#pragma unroll
    for (int j = 0; j < NC; ++j)
        kr[j] = *(const float4*)(K + ((size_t)j * NN + n) * 128 + lane * 4);

    const float scale = 0.08838834764831845f;  // 1/sqrt(128)
#pragma unroll
    for (int c = 0; c < NC; ++c) {
        float4 qc = *(const float4*)(&q_s[c][lane * 4]);
#pragma unroll
        for (int j = 0; j < NC; ++j) {
            float p = qc.x * kr[j].x + qc.y * kr[j].y + qc.z * kr[j].z + qc.w * kr[j].w;
            p += __shfl_xor_sync(0xffffffffu, p, 16);
            p += __shfl_xor_sync(0xffffffffu, p, 8);
            p += __shfl_xor_sync(0xffffffffu, p, 4);
            p += __shfl_xor_sync(0xffffffffu, p, 2);
            p += __shfl_xor_sync(0xffffffffu, p, 1);
            if (lane == 0) s_s[w][c][j] = p * scale;
        }
    }
    __syncwarp();
    if (lane < NC) {
        float m = -1e30f;
#pragma unroll
        for (int j = 0; j < NC; ++j) m = fmaxf(m, s_s[w][lane][j]);
        float e[NC], sum = 0.f;
#pragma unroll
        for (int j = 0; j < NC; ++j) { e[j] = expf(s_s[w][lane][j] - m); sum += e[j]; }
        float inv = 1.f / sum;
#pragma unroll
        for (int j = 0; j < NC; ++j) s_s[w][lane][j] = e[j] * inv;
    }
    __syncwarp();

    float4 acc[NC];
#pragma unroll
    for (int c = 0; c < NC; ++c) acc[c] = make_float4(0.f, 0.f, 0.f, 0.f);
#pragma unroll
    for (int j = 0; j < NC; ++j) {
        float4 vj = *(const float4*)(V + ((size_t)j * NN + n) * 128 + lane * 4);
#pragma unroll
        for (int c = 0; c < NC; ++c) {
            float sc = s_s[w][c][j];
            acc[c].x += sc * vj.x; acc[c].y += sc * vj.y;
            acc[c].z += sc * vj.z; acc[c].w += sc * vj.w;
        }
    }
#pragma unroll
    for (int c = 0; c < NC; ++c) {
        float4 v = acc[c];
        if (doRelu) {
            v.x = fmaxf(v.x, 0.f); v.y = fmaxf(v.y, 0.f);
            v.z = fmaxf(v.z, 0.f); v.w = fmaxf(v.w, 0.f);
        }
        *(float4*)(out + ((size_t)c * NN + n) * 128 + lane * 4) = v;
    }
}

// ---------------- ori-branch permutation -----------------------------------
__global__ void board_kernel(const int* __restrict__ src_ids) {
    int i = blockIdx.x * blockDim.x + threadIdx.x;
    if (i < NN) g_board[src_ids[i]] = i;
}

__global__ void __launch_bounds__(256) permute_kernel(const float* __restrict__ in,
                                                      const int* __restrict__ dst_ids,
                                                      float* __restrict__ out, int doRelu) {
    int gw = blockIdx.x * 8 + (threadIdx.x >> 5);
    if (gw >= NN) return;
    int lane = threadIdx.x & 31;
    int p = g_board[dst_ids[gw]];
    float4 v = *(const float4*)(in + (size_t)p * 128 + lane * 4);
    if (doRelu) {
        v.x = fmaxf(v.x, 0.f); v.y = fmaxf(v.y, 0.f);
        v.z = fmaxf(v.z, 0.f); v.w = fmaxf(v.w, 0.f);
    }
    *(float4*)(out + (size_t)gw * 128 + lane * 4) = v;
}

// ---------------- orchestration --------------------------------------------
extern "C" void kernel_launch(void* const* d_in, const int* in_sizes, int n_in,
                              void* d_out, int out_size) {
    const float* gfe0  = (const float*)d_in[0];
    const float* ofe0  = (const float*)d_in[1];
    const float* label = (const float*)d_in[2];
    const float* Wl[2] = {(const float*)d_in[3], (const float*)d_in[5]};
    const float* bl[2] = {(const float*)d_in[4], (const float*)d_in[6]};
    const float* Wq = (const float*)d_in[7];
    const float* bq = (const float*)d_in[8];
    const float* Wk = (const float*)d_in[9];
    const float* bk = (const float*)d_in[10];
    const float* Wv = (const float*)d_in[11];
    const float* bv = (const float*)d_in[12];
    const int* ge      = (const int*)d_in[13];
    const int* oe      = (const int*)d_in[14];
    const int* src_ids = (const int*)d_in[15];
    const int* dst_ids = (const int*)d_in[16];

    float* out_gfe = (float*)d_out;
    float* out_ofe = out_gfe + (size_t)NC * NN * ND;

    float *bufA, *bufB, *Kb, *Vb, *xw, *oxw, *otmp, *ofeB;
    int* cnt;
    cudaGetSymbolAddress((void**)&bufA, g_bufA);
    cudaGetSymbolAddress((void**)&bufB, g_bufB);
    cudaGetSymbolAddress((void**)&Kb,   g_K);
    cudaGetSymbolAddress((void**)&Vb,   g_V);
    cudaGetSymbolAddress((void**)&xw,   g_xw);
    cudaGetSymbolAddress((void**)&oxw,  g_oxw);
    cudaGetSymbolAddress((void**)&otmp, g_otmp);
    cudaGetSymbolAddress((void**)&ofeB, g_ofe);
    cudaGetSymbolAddress((void**)&cnt,  g_cnt);

    cudaFuncSetAttribute(gemm128, cudaFuncAttributeMaxDynamicSharedMemorySize, GEMM_SMEM);

    q_kernel<<<1, 128>>>(label, Wq, bq);

    const float* cur_g = gfe0;
    const float* cur_o = ofe0;

    for (int layer = 0; layer < 2; ++layer) {
        const float* W = Wl[layer];
        const float* b = bl[layer];
        int relu = (layer == 0);

        // ---- graph branch: GCN over 10 class graphs (batched) ----
        gemm128<<<(NC * NN + 127) / 128, 256, GEMM_SMEM>>>(cur_g, W, nullptr, xw, NC * NN);
        zero_int<<<(NC * NN + 255) / 256, 256>>>(cnt, NC * NN);
        count_graph<<<(NC * NE + 255) / 256, 256>>>(ge, layer);
        scan_kernel<<<NC, 1024>>>();
        fill_graph<<<(NC * NE + 255) / 256, 256>>>(ge, layer);
        gather_kernel<<<(NC * NN + 7) / 8, 256>>>(xw, b, bufA, NC);

        // ---- attention across classes ----
        gemm128<<<(NC * NN + 127) / 128, 256, GEMM_SMEM>>>(bufA, Wk, bk, Kb, NC * NN);
        gemm128<<<(NC * NN + 127) / 128, 256, GEMM_SMEM>>>(bufA, Wv, bv, Vb, NC * NN);
        float* gout = relu ? bufB : out_gfe;
        attn_kernel<<<(NN + 3) / 4, 128>>>(Kb, Vb, gout, relu);
        cur_g = bufB;

        // ---- original-graph branch ----
        gemm128<<<(NN + 127) / 128, 256, GEMM_SMEM>>>(cur_o, W, nullptr, oxw, NN);
        zero_int<<<(NN + 255) / 256, 256>>>(cnt, NN);
        count_ori<<<(NE + 255) / 256, 256>>>(oe, layer);
        scan_kernel<<<1, 1024>>>();
        fill_ori<<<(NE + 255) / 256, 256>>>(oe, layer);
        gather_kernel<<<(NN + 7) / 8, 256>>>(oxw, b, otmp, 1);
        board_kernel<<<(NN + 255) / 256, 256>>>(src_ids + (size_t)layer * NN);
        float* oout = relu ? ofeB : out_ofe;
        permute_kernel<<<(NN + 7) / 8, 256>>>(otmp, dst_ids + (size_t)layer * NN, oout, relu);
        cur_o = ofeB;
    }
}

// round 2
// speedup vs baseline: 1.3762x; 1.3762x over previous
#include <cuda_runtime.h>
#include <math.h>

#define NN 50000
#define NC 10
#define NL 2
#define NE 800000
#define ND 128

// ---------------- scratch (device globals; no runtime allocation) ----------
__device__ float g_bufA[(size_t)NC * NN * ND];   // GCN output (attention input)
__device__ float g_bufB[(size_t)NC * NN * ND];   // attention+Wv output (layer 0)
__device__ float g_mixed[(size_t)NC * NN * ND];  // scores @ feat
__device__ float g_xw[(size_t)NC * NN * ND];     // (X @ W) * dinv[row]
__device__ float g_oxw[(size_t)NN * ND];
__device__ float g_ofe[(size_t)NN * ND];
__device__ float g_qt[NC * ND];                  // Wk @ q[c]
__device__ float g_dinv[NC * NN];
__device__ int   g_cnt[NC * NN];
__device__ int   g_off[NC * NN];
__device__ int   g_cur[NC * NN];
__device__ int   g_csr[(size_t)NC * NE];
__device__ int   g_board[NN];
__device__ int   g_rel[NN];

// ---------------- f32x2 helpers --------------------------------------------
__device__ __forceinline__ unsigned long long splat2(float a) {
    unsigned long long r;
    asm("mov.b64 %0, {%1, %1};" : "=l"(r) : "f"(a));
    return r;
}
__device__ __forceinline__ float2 ull2f2(unsigned long long u) {
    float2 f;
    asm("mov.b64 {%0, %1}, %2;" : "=f"(f.x), "=f"(f.y) : "l"(u));
    return f;
}
#define FMA2(d, a, b) asm("fma.rn.f32x2 %0, %1, %2, %0;" : "+l"(d) : "l"(a), "l"(b))

// ---------------- GEMM: C[M,128] = (A[M,128] @ W[128,128]) * rs[row] + bias --
#define GEMM_SMEM (2 * 128 * 132 * 4)

__global__ void __launch_bounds__(256) gemm128(const float* __restrict__ A,
                                               const float* __restrict__ W,
                                               const float* __restrict__ bias,
                                               const float* __restrict__ rowscale,
                                               float* __restrict__ Cmat, int M,
                                               int doRelu) {
    extern __shared__ float sm[];
    float* As = sm;              // [128][132] (row, k)
    float* Ws = sm + 128 * 132;  // [128][132] (k, j)

    const int tid  = threadIdx.x;
    const int row0 = blockIdx.x * 128;

#pragma unroll
    for (int it = 0; it < 16; ++it) {
        int idx = tid + it * 256;          // 0..4095 float4 slots
        int r   = idx >> 5;
        int k4  = idx & 31;
        float4 v = make_float4(0.f, 0.f, 0.f, 0.f);
        int gr = row0 + r;
        if (gr < M) v = *(const float4*)(A + (size_t)gr * 128 + k4 * 4);
        *(float4*)(As + r * 132 + k4 * 4) = v;
        float4 w = *(const float4*)(W + (size_t)idx * 4);
        *(float4*)(Ws + r * 132 + k4 * 4) = w;
    }
    __syncthreads();

    const int ty = tid >> 4, tx = tid & 15;
    const int i0 = ty * 8, j0 = tx * 8;

    unsigned long long acc[8][4];
#pragma unroll
    for (int r = 0; r < 8; ++r)
#pragma unroll
        for (int p = 0; p < 4; ++p) acc[r][p] = 0ULL;

#pragma unroll 2
    for (int k4 = 0; k4 < 128; k4 += 4) {
        float4 a[8];
#pragma unroll
        for (int r = 0; r < 8; ++r)
            a[r] = *(const float4*)(As + (i0 + r) * 132 + k4);
#pragma unroll
        for (int kk = 0; kk < 4; ++kk) {
            ulonglong2 w0 = *(const ulonglong2*)(Ws + (k4 + kk) * 132 + j0);
            ulonglong2 w1 = *(const ulonglong2*)(Ws + (k4 + kk) * 132 + j0 + 4);
#pragma unroll
            for (int r = 0; r < 8; ++r) {
                unsigned long long a2 = splat2(((const float*)&a[r])[kk]);
                FMA2(acc[r][0], a2, w0.x);
                FMA2(acc[r][1], a2, w0.y);
                FMA2(acc[r][2], a2, w1.x);
                FMA2(acc[r][3], a2, w1.y);
            }
        }
    }

    float bj[8];
#pragma unroll
    for (int jj = 0; jj < 8; ++jj) bj[jj] = bias ? bias[j0 + jj] : 0.f;

#pragma unroll
    for (int r = 0; r < 8; ++r) {
        int gr = row0 + i0 + r;
        if (gr < M) {
            float rs = rowscale ? rowscale[gr] : 1.f;
            float2 f0 = ull2f2(acc[r][0]);
            float2 f1 = ull2f2(acc[r][1]);
            float2 f2 = ull2f2(acc[r][2]);
            float2 f3 = ull2f2(acc[r][3]);
            float o[8] = {f0.x * rs + bj[0], f0.y * rs + bj[1],
                          f1.x * rs + bj[2], f1.y * rs + bj[3],
                          f2.x * rs + bj[4], f2.y * rs + bj[5],
                          f3.x * rs + bj[6], f3.y * rs + bj[7]};
            if (doRelu) {
#pragma unroll
                for (int jj = 0; jj < 8; ++jj) o[jj] = fmaxf(o[jj], 0.f);
            }
            *(float4*)(Cmat + (size_t)gr * 128 + j0)     = make_float4(o[0], o[1], o[2], o[3]);
            *(float4*)(Cmat + (size_t)gr * 128 + j0 + 4) = make_float4(o[4], o[5], o[6], o[7]);
        }
    }
}

// ---------------- CSR construction -----------------------------------------
__global__ void zero_int(int* p, int n) {
    int i = blockIdx.x * blockDim.x + threadIdx.x;
    if (i < n) p[i] = 0;
}

__global__ void count_graph(const int* __restrict__ ge, int layer) {
    int i = blockIdx.x * blockDim.x + threadIdx.x;
    if (i >= NC * NE) return;
    int c = i / NE, e = i - c * NE;
    int dst = ge[(size_t)((c * NL + layer) * 2 + 1) * NE + e];
    atomicAdd(&g_cnt[c * NN + dst], 1);
}

__global__ void fill_graph(const int* __restrict__ ge, int layer) {
    int i = blockIdx.x * blockDim.x + threadIdx.x;
    if (i >= NC * NE) return;
    int c = i / NE, e = i - c * NE;
    int src = ge[(size_t)((c * NL + layer) * 2 + 0) * NE + e];
    int dst = ge[(size_t)((c * NL + layer) * 2 + 1) * NE + e];
    int pos = atomicAdd(&g_cur[c * NN + dst], 1);
    g_csr[(size_t)c * NE + pos] = src;
}

__global__ void count_ori(const int* __restrict__ oe, int layer) {
    int i = blockIdx.x * blockDim.x + threadIdx.x;
    if (i >= NE) return;
    int dst = oe[(size_t)(layer * 2 + 1) * NE + i];
    atomicAdd(&g_cnt[dst], 1);
}

__global__ void fill_ori(const int* __restrict__ oe, int layer) {
    int i = blockIdx.x * blockDim.x + threadIdx.x;
    if (i >= NE) return;
    int src = oe[(size_t)(layer * 2 + 0) * NE + i];
    int dst = oe[(size_t)(layer * 2 + 1) * NE + i];
    int pos = atomicAdd(&g_cur[dst], 1);
    g_csr[pos] = src;
}

// one block per class: exclusive scan of counts -> offsets/cursor, plus dinv
__global__ void scan_kernel() {
    __shared__ int part[1024];
    const int c = blockIdx.x, t = threadIdx.x;
    const int* cnt = g_cnt + c * NN;
    const int CH = (NN + 1023) / 1024;
    int s0 = t * CH;
    int s1 = s0 + CH; if (s1 > NN) s1 = NN;
    int sum = 0;
    for (int n = s0; n < s1; ++n) sum += cnt[n];
    part[t] = sum;
    __syncthreads();
    for (int d = 1; d < 1024; d <<= 1) {
        int v = (t >= d) ? part[t - d] : 0;
        __syncthreads();
        part[t] += v;
        __syncthreads();
    }
    int run = (t == 0) ? 0 : part[t - 1];
    for (int n = s0; n < s1; ++n) {
        int cv = cnt[n];
        g_off[c * NN + n]  = run;
        g_cur[c * NN + n]  = run;
        g_dinv[c * NN + n] = rsqrtf((float)(1 + cv));
        run += cv;
    }
}

// ---------------- GCN gather (xw pre-scaled by dinv[src] in GEMM epilogue) --
// out[n] = b + dinv[n] * ( xws[n] + sum_{s in CSR(n)} xws[s] )
__global__ void __launch_bounds__(256) gather_graph(const float* __restrict__ xws,
                                                    const float* __restrict__ bias,
                                                    float* __restrict__ out) {
    int gw = blockIdx.x * 8 + (threadIdx.x >> 5);
    if (gw >= NC * NN) return;
    int lane = threadIdx.x & 31;
    int c = gw / NN;
    int n = gw - c * NN;
    const float* xwc = xws + (size_t)c * NN * 128;
    float4 acc = *(const float4*)(xwc + (size_t)n * 128 + lane * 4);
    int beg = g_off[gw];
    int end = beg + g_cnt[gw];
    const int* csr = g_csr + (size_t)c * NE;
    int j = beg;
    for (; j + 3 < end; j += 4) {
        int s0 = csr[j], s1 = csr[j + 1], s2 = csr[j + 2], s3 = csr[j + 3];
        float4 a0 = *(const float4*)(xwc + (size_t)s0 * 128 + lane * 4);
        float4 a1 = *(const float4*)(xwc + (size_t)s1 * 128 + lane * 4);
        float4 a2 = *(const float4*)(xwc + (size_t)s2 * 128 + lane * 4);
        float4 a3 = *(const float4*)(xwc + (size_t)s3 * 128 + lane * 4);
        acc.x += a0.x + a1.x + a2.x + a3.x;
        acc.y += a0.y + a1.y + a2.y + a3.y;
        acc.z += a0.z + a1.z + a2.z + a3.z;
        acc.w += a0.w + a1.w + a2.w + a3.w;
    }
    for (; j < end; ++j) {
        int s0 = csr[j];
        float4 a0 = *(const float4*)(xwc + (size_t)s0 * 128 + lane * 4);
        acc.x += a0.x; acc.y += a0.y; acc.z += a0.z; acc.w += a0.w;
    }
    float dv = g_dinv[gw];
    float4 b4 = *(const float4*)(bias + lane * 4);
    float4 o = make_float4(b4.x + acc.x * dv, b4.y + acc.y * dv,
                           b4.z + acc.z * dv, b4.w + acc.w * dv);
    *(float4*)(out + (size_t)gw * 128 + lane * 4) = o;
}

// ori branch: output row i aggregates node rel[i]; optional relu (fused permute)
__global__ void __launch_bounds__(256) gather_ori(const float* __restrict__ xws,
                                                  const float* __restrict__ bias,
                                                  float* __restrict__ out, int doRelu) {
    int gw = blockIdx.x * 8 + (threadIdx.x >> 5);
    if (gw >= NN) return;
    int lane = threadIdx.x & 31;
    int n = g_rel[gw];
    float4 acc = *(const float4*)(xws + (size_t)n * 128 + lane * 4);
    int beg = g_off[n];
    int end = beg + g_cnt[n];
    int j = beg;
    for (; j + 3 < end; j += 4) {
        int s0 = g_csr[j], s1 = g_csr[j + 1], s2 = g_csr[j + 2], s3 = g_csr[j + 3];
        float4 a0 = *(const float4*)(xws + (size_t)s0 * 128 + lane * 4);
        float4 a1 = *(const float4*)(xws + (size_t)s1 * 128 + lane * 4);
        float4 a2 = *(const float4*)(xws + (size_t)s2 * 128 + lane * 4);
        float4 a3 = *(const float4*)(xws + (size_t)s3 * 128 + lane * 4);
        acc.x += a0.x + a1.x + a2.x + a3.x;
        acc.y += a0.y + a1.y + a2.y + a3.y;
        acc.z += a0.z + a1.z + a2.z + a3.z;
        acc.w += a0.w + a1.w + a2.w + a3.w;
    }
    for (; j < end; ++j) {
        int s0 = g_csr[j];
        float4 a0 = *(const float4*)(xws + (size_t)s0 * 128 + lane * 4);
        acc.x += a0.x; acc.y += a0.y; acc.z += a0.z; acc.w += a0.w;
    }
    float dv = g_dinv[n];
    float4 b4 = *(const float4*)(bias + lane * 4);
    float4 o = make_float4(b4.x + acc.x * dv, b4.y + acc.y * dv,
                           b4.z + acc.z * dv, b4.w + acc.w * dv);
    if (doRelu) {
        o.x = fmaxf(o.x, 0.f); o.y = fmaxf(o.y, 0.f);
        o.z = fmaxf(o.z, 0.f); o.w = fmaxf(o.w, 0.f);
    }
    *(float4*)(out + (size_t)gw * 128 + lane * 4) = o;
}

// ---------------- qt[c] = Wk @ (label[c] @ Wq + bq) -------------------------
__global__ void q_kernel(const float* __restrict__ label,
                         const float* __restrict__ Wq,
                         const float* __restrict__ bq,
                         const float* __restrict__ Wk) {
    __shared__ float Ls[NC * 128];
    __shared__ float Qs[NC * 128];
    int t = threadIdx.x;  // 128 threads
    for (int i = t; i < NC * 128; i += 128) Ls[i] = label[i];
    __syncthreads();
    for (int c = 0; c < NC; ++c) {
        float acc = bq[t];
#pragma unroll 8
        for (int h = 0; h < 128; ++h) acc += Ls[c * 128 + h] * Wq[h * 128 + t];
        Qs[c * 128 + t] = acc;
    }
    __syncthreads();
    // qt[c][t] = sum_j Wk[t][j] * q[c][j]
    float acc[NC];
#pragma unroll
    for (int c = 0; c < NC; ++c) acc[c] = 0.f;
    for (int j = 0; j < 128; ++j) {
        float wv = Wk[t * 128 + j];
#pragma unroll
        for (int c = 0; c < NC; ++c) acc[c] += wv * Qs[c * 128 + j];
    }
#pragma unroll
    for (int c = 0; c < NC; ++c) g_qt[c * 128 + t] = acc[c];
}

// ---------------- attention scores + mix: mixed = softmax(qt . feat) @ feat -
__global__ void __launch_bounds__(128) attn_mix(const float* __restrict__ feat,
                                                float* __restrict__ mixed) {
    __shared__ float qt_s[NC][128];
    __shared__ float s_s[4][NC][NC];
    int tid = threadIdx.x;
    for (int i = tid; i < NC * 128; i += 128) qt_s[i >> 7][i & 127] = g_qt[i];
    __syncthreads();
    int w = tid >> 5, lane = tid & 31;
    int n = blockIdx.x * 4 + w;
    if (n >= NN) return;

    float4 fr[NC];
#pragma unroll
    for (int k = 0; k < NC; ++k)
        fr[k] = *(const float4*)(feat + ((size_t)k * NN + n) * 128 + lane * 4);

#pragma unroll
    for (int c = 0; c < NC; ++c) {
        float4 qc = *(const float4*)(&qt_s[c][lane * 4]);
#pragma unroll
        for (int k = 0; k < NC; ++k) {
            float p = qc.x * fr[k].x + qc.y * fr[k].y + qc.z * fr[k].z + qc.w * fr[k].w;
            p += __shfl_xor_sync(0xffffffffu, p, 16);
            p += __shfl_xor_sync(0xffffffffu, p, 8);
            p += __shfl_xor_sync(0xffffffffu, p, 4);
            p += __shfl_xor_sync(0xffffffffu, p, 2);
            p += __shfl_xor_sync(0xffffffffu, p, 1);
            if (lane == 0) s_s[w][c][k] = p;
        }
    }
    __syncwarp();
    const float scale = 0.08838834764831845f;  // 1/sqrt(128)
    if (lane < NC) {
        float m = -1e30f;
#pragma unroll
        for (int k = 0; k < NC; ++k) m = fmaxf(m, s_s[w][lane][k]);
        float e[NC], sum = 0.f;
#pragma unroll
        for (int k = 0; k < NC; ++k) {
            e[k] = expf((s_s[w][lane][k] - m) * scale);
            sum += e[k];
        }
        float inv = 1.f / sum;
#pragma unroll
        for (int k = 0; k < NC; ++k) s_s[w][lane][k] = e[k] * inv;
    }
    __syncwarp();

    float4 acc[NC];
#pragma unroll
    for (int c = 0; c < NC; ++c) acc[c] = make_float4(0.f, 0.f, 0.f, 0.f);
#pragma unroll
    for (int k = 0; k < NC; ++k) {
        float4 vk = fr[k];
#pragma unroll
        for (int c = 0; c < NC; ++c) {
            float sc = s_s[w][c][k];
            acc[c].x += sc * vk.x; acc[c].y += sc * vk.y;
            acc[c].z += sc * vk.z; acc[c].w += sc * vk.w;
        }
    }
#pragma unroll
    for (int c = 0; c < NC; ++c)
        *(float4*)(mixed + ((size_t)c * NN + n) * 128 + lane * 4) = acc[c];
}

// ---------------- ori-branch relative index --------------------------------
__global__ void board_kernel(const int* __restrict__ src_ids) {
    int i = blockIdx.x * blockDim.x + threadIdx.x;
    if (i < NN) g_board[src_ids[i]] = i;
}
__global__ void rel_kernel(const int* __restrict__ dst_ids) {
    int i = blockIdx.x * blockDim.x + threadIdx.x;
    if (i < NN) g_rel[i] = g_board[dst_ids[i]];
}

// ---------------- orchestration --------------------------------------------
extern "C" void kernel_launch(void* const* d_in, const int* in_sizes, int n_in,
                              void* d_out, int out_size) {
    const float* gfe0  = (const float*)d_in[0];
    const float* ofe0  = (const float*)d_in[1];
    const float* label = (const float*)d_in[2];
    const float* Wl[2] = {(const float*)d_in[3], (const float*)d_in[5]};
    const float* bl[2] = {(const float*)d_in[4], (const float*)d_in[6]};
    const float* Wq = (const float*)d_in[7];
    const float* bq = (const float*)d_in[8];
    const float* Wk = (const float*)d_in[9];
    const float* Wv = (const float*)d_in[11];
    const float* bv = (const float*)d_in[12];
    const int* ge      = (const int*)d_in[13];
    const int* oe      = (const int*)d_in[14];
    const int* src_ids = (const int*)d_in[15];
    const int* dst_ids = (const int*)d_in[16];

    float* out_gfe = (float*)d_out;
    float* out_ofe = out_gfe + (size_t)NC * NN * ND;

    float *bufA, *bufB, *mixed, *xw, *oxw, *ofeB, *dinv;
    int* cnt;
    cudaGetSymbolAddress((void**)&bufA,  g_bufA);
    cudaGetSymbolAddress((void**)&bufB,  g_bufB);
    cudaGetSymbolAddress((void**)&mixed, g_mixed);
    cudaGetSymbolAddress((void**)&xw,    g_xw);
    cudaGetSymbolAddress((void**)&oxw,   g_oxw);
    cudaGetSymbolAddress((void**)&ofeB,  g_ofe);
    cudaGetSymbolAddress((void**)&dinv,  g_dinv);
    cudaGetSymbolAddress((void**)&cnt,   g_cnt);

    cudaFuncSetAttribute(gemm128, cudaFuncAttributeMaxDynamicSharedMemorySize, GEMM_SMEM);

    q_kernel<<<1, 128>>>(label, Wq, bq, Wk);

    const float* cur_g = gfe0;
    const float* cur_o = ofe0;

    for (int layer = 0; layer < 2; ++layer) {
        const float* W = Wl[layer];
        const float* b = bl[layer];
        int relu = (layer == 0);

        // ---- graph branch: CSR first (so GEMM can pre-scale by dinv) ----
        zero_int<<<(NC * NN + 255) / 256, 256>>>(cnt, NC * NN);
        count_graph<<<(NC * NE + 255) / 256, 256>>>(ge, layer);
        scan_kernel<<<NC, 1024>>>();
        fill_graph<<<(NC * NE + 255) / 256, 256>>>(ge, layer);
        gemm128<<<(NC * NN + 127) / 128, 256, GEMM_SMEM>>>(cur_g, W, nullptr, dinv, xw, NC * NN, 0);
        gather_graph<<<(NC * NN + 7) / 8, 256>>>(xw, b, bufA);

        // ---- attention across classes (K GEMM eliminated; V GEMM moved) ----
        attn_mix<<<(NN + 3) / 4, 128>>>(bufA, mixed);
        float* gout = relu ? bufB : out_gfe;
        gemm128<<<(NC * NN + 127) / 128, 256, GEMM_SMEM>>>(mixed, Wv, bv, nullptr, gout, NC * NN, relu);
        cur_g = bufB;

        // ---- original-graph branch ----
        zero_int<<<(NN + 255) / 256, 256>>>(cnt, NN);
        count_ori<<<(NE + 255) / 256, 256>>>(oe, layer);
        scan_kernel<<<1, 1024>>>();
        fill_ori<<<(NE + 255) / 256, 256>>>(oe, layer);
        gemm128<<<(NN + 127) / 128, 256, GEMM_SMEM>>>(cur_o, W, nullptr, dinv, oxw, NN, 0);
        board_kernel<<<(NN + 255) / 256, 256>>>(src_ids + (size_t)layer * NN);
        rel_kernel<<<(NN + 255) / 256, 256>>>(dst_ids + (size_t)layer * NN);
        float* oout = relu ? ofeB : out_ofe;
        gather_ori<<<(NN + 7) / 8, 256>>>(oxw, b, oout, relu);
        cur_o = ofeB;
    }
}

// round 3
// speedup vs baseline: 1.5684x; 1.1397x over previous
#include <cuda_runtime.h>
#include <math.h>

#define NN 50000
#define NC 10
#define NL 2
#define NE 800000
#define ND 128

#define NTOT (NC * NN + NN)              // flat node slots: 10 class graphs + ori
#define TE   ((size_t)NC * NE + NE)      // total edges per layer (graph + ori)
#define SCAN_ITEMS 2048
#define SCAN_BLOCKS ((NTOT + SCAN_ITEMS - 1) / SCAN_ITEMS)   // 269

// ---------------- scratch (device globals; no runtime allocation) ----------
__device__ float g_bufA[(size_t)NC * NN * ND];   // GCN output (attention input)
__device__ float g_bufB[(size_t)NC * NN * ND];   // attention+Wv output (layer 0)
__device__ float g_mixed[(size_t)NC * NN * ND];  // scores @ feat
__device__ float g_xw[(size_t)NC * NN * ND];     // (X @ W) * dinv[row]
__device__ float g_oxw[(size_t)NN * ND];
__device__ float g_ofe[(size_t)NN * ND];
__device__ float g_qt[NC * ND];                  // Wk @ q[c]
__device__ float g_dinv[NTOT];
__device__ int   g_cnt[NTOT];
__device__ int   g_off[NTOT];
__device__ int   g_cur[NTOT];
__device__ int   g_part[512];
__device__ int   g_csr[TE];
__device__ int   g_board[NN];
__device__ int   g_rel[NN];

// ---------------- f32x2 helpers --------------------------------------------
__device__ __forceinline__ unsigned long long splat2(float a) {
    unsigned long long r;
    asm("mov.b64 %0, {%1, %1};" : "=l"(r) : "f"(a));
    return r;
}
__device__ __forceinline__ float2 ull2f2(unsigned long long u) {
    float2 f;
    asm("mov.b64 {%0, %1}, %2;" : "=f"(f.x), "=f"(f.y) : "l"(u));
    return f;
}
#define FMA2(d, a, b) asm("fma.rn.f32x2 %0, %1, %2, %0;" : "+l"(d) : "l"(a), "l"(b))

// ---------------- GEMM: C[M,128] = (A[M,128] @ W[128,128]) * rs[row] + bias --
#define GEMM_SMEM (2 * 128 * 132 * 4)

__global__ void __launch_bounds__(256) gemm128(const float* __restrict__ A,
                                               const float* __restrict__ W,
                                               const float* __restrict__ bias,
                                               const float* __restrict__ rowscale,
                                               float* __restrict__ Cmat, int M,
                                               int doRelu) {
    extern __shared__ float sm[];
    float* As = sm;              // [128][132] (row, k)
    float* Ws = sm + 128 * 132;  // [128][132] (k, j)

    const int tid  = threadIdx.x;
    const int row0 = blockIdx.x * 128;

#pragma unroll
    for (int it = 0; it < 16; ++it) {
        int idx = tid + it * 256;          // 0..4095 float4 slots
        int r   = idx >> 5;
        int k4  = idx & 31;
        float4 v = make_float4(0.f, 0.f, 0.f, 0.f);
        int gr = row0 + r;
        if (gr < M) v = *(const float4*)(A + (size_t)gr * 128 + k4 * 4);
        *(float4*)(As + r * 132 + k4 * 4) = v;
        float4 w = *(const float4*)(W + (size_t)idx * 4);
        *(float4*)(Ws + r * 132 + k4 * 4) = w;
    }
    __syncthreads();

    const int ty = tid >> 4, tx = tid & 15;
    const int i0 = ty * 8, j0 = tx * 8;

    unsigned long long acc[8][4];
#pragma unroll
    for (int r = 0; r < 8; ++r)
#pragma unroll
        for (int p = 0; p < 4; ++p) acc[r][p] = 0ULL;

#pragma unroll 2
    for (int k4 = 0; k4 < 128; k4 += 4) {
        float4 a[8];
#pragma unroll
        for (int r = 0; r < 8; ++r)
            a[r] = *(const float4*)(As + (i0 + r) * 132 + k4);
#pragma unroll
        for (int kk = 0; kk < 4; ++kk) {
            ulonglong2 w0 = *(const ulonglong2*)(Ws + (k4 + kk) * 132 + j0);
            ulonglong2 w1 = *(const ulonglong2*)(Ws + (k4 + kk) * 132 + j0 + 4);
#pragma unroll
            for (int r = 0; r < 8; ++r) {
                unsigned long long a2 = splat2(((const float*)&a[r])[kk]);
                FMA2(acc[r][0], a2, w0.x);
                FMA2(acc[r][1], a2, w0.y);
                FMA2(acc[r][2], a2, w1.x);
                FMA2(acc[r][3], a2, w1.y);
            }
        }
    }

    float bj[8];
#pragma unroll
    for (int jj = 0; jj < 8; ++jj) bj[jj] = bias ? bias[j0 + jj] : 0.f;

#pragma unroll
    for (int r = 0; r < 8; ++r) {
        int gr = row0 + i0 + r;
        if (gr < M) {
            float rs = rowscale ? rowscale[gr] : 1.f;
            float2 f0 = ull2f2(acc[r][0]);
            float2 f1 = ull2f2(acc[r][1]);
            float2 f2 = ull2f2(acc[r][2]);
            float2 f3 = ull2f2(acc[r][3]);
            float o[8] = {f0.x * rs + bj[0], f0.y * rs + bj[1],
                          f1.x * rs + bj[2], f1.y * rs + bj[3],
                          f2.x * rs + bj[4], f2.y * rs + bj[5],
                          f3.x * rs + bj[6], f3.y * rs + bj[7]};
            if (doRelu) {
#pragma unroll
                for (int jj = 0; jj < 8; ++jj) o[jj] = fmaxf(o[jj], 0.f);
            }
            *(float4*)(Cmat + (size_t)gr * 128 + j0)     = make_float4(o[0], o[1], o[2], o[3]);
            *(float4*)(Cmat + (size_t)gr * 128 + j0 + 4) = make_float4(o[4], o[5], o[6], o[7]);
        }
    }
}

// ---------------- CSR construction (graph + ori merged, flat offsets) -------
__global__ void zero_cnt() {
    int i = blockIdx.x * blockDim.x + threadIdx.x;
    if (i < NTOT) g_cnt[i] = 0;
}

// one thread per edge over all NC graphs + ori graph
__global__ void count_all(const int* __restrict__ ge, const int* __restrict__ oe,
                          int layer) {
    size_t i = (size_t)blockIdx.x * blockDim.x + threadIdx.x;
    if (i >= TE) return;
    int idx;
    if (i < (size_t)NC * NE) {
        int c = (int)(i / NE);
        int e = (int)(i - (size_t)c * NE);
        int dst = ge[(size_t)((c * NL + layer) * 2 + 1) * NE + e];
        idx = c * NN + dst;
    } else {
        int e = (int)(i - (size_t)NC * NE);
        int dst = oe[(size_t)(layer * 2 + 1) * NE + e];
        idx = NC * NN + dst;
    }
    atomicAdd(&g_cnt[idx], 1);
}

__global__ void fill_all(const int* __restrict__ ge, const int* __restrict__ oe,
                         int layer) {
    size_t i = (size_t)blockIdx.x * blockDim.x + threadIdx.x;
    if (i >= TE) return;
    int idx, src;
    if (i < (size_t)NC * NE) {
        int c = (int)(i / NE);
        int e = (int)(i - (size_t)c * NE);
        src     = ge[(size_t)((c * NL + layer) * 2 + 0) * NE + e];
        int dst = ge[(size_t)((c * NL + layer) * 2 + 1) * NE + e];
        idx = c * NN + dst;
    } else {
        int e = (int)(i - (size_t)NC * NE);
        src     = oe[(size_t)(layer * 2 + 0) * NE + e];
        int dst = oe[(size_t)(layer * 2 + 1) * NE + e];
        idx = NC * NN + dst;
    }
    int pos = atomicAdd(&g_cur[idx], 1);   // flat global position
    g_csr[pos] = src;
}

// ---- parallel flat exclusive scan over g_cnt[NTOT] -> g_off/g_cur/g_dinv ----
__global__ void __launch_bounds__(256) scan_p1() {
    __shared__ int wsum[8];
    int b = blockIdx.x, t = threadIdx.x;
    int base = b * SCAN_ITEMS + t * 8;
    int s = 0;
#pragma unroll
    for (int k = 0; k < 8; ++k) {
        int g = base + k;
        if (g < NTOT) s += g_cnt[g];
    }
#pragma unroll
    for (int d = 16; d; d >>= 1) s += __shfl_xor_sync(0xffffffffu, s, d);
    if ((t & 31) == 0) wsum[t >> 5] = s;
    __syncthreads();
    if (t == 0) {
        int tot = 0;
#pragma unroll
        for (int w = 0; w < 8; ++w) tot += wsum[w];
        g_part[b] = tot;
    }
}

__global__ void __launch_bounds__(512) scan_p2(int nb) {
    __shared__ int s[512];
    int t = threadIdx.x;
    int v = (t < nb) ? g_part[t] : 0;
    s[t] = v;
    __syncthreads();
#pragma unroll
    for (int d = 1; d < 512; d <<= 1) {
        int u = (t >= d) ? s[t - d] : 0;
        __syncthreads();
        s[t] += u;
        __syncthreads();
    }
    if (t < nb) g_part[t] = s[t] - v;   // exclusive
}

__global__ void __launch_bounds__(256) scan_p3() {
    __shared__ int ts[256];
    int b = blockIdx.x, t = threadIdx.x;
    int base = b * SCAN_ITEMS + t * 8;
    int v[8];
    int s = 0;
#pragma unroll
    for (int k = 0; k < 8; ++k) {
        int g = base + k;
        v[k] = (g < NTOT) ? g_cnt[g] : 0;
        s += v[k];
    }
    ts[t] = s;
    __syncthreads();
#pragma unroll
    for (int d = 1; d < 256; d <<= 1) {
        int u = (t >= d) ? ts[t - d] : 0;
        __syncthreads();
        ts[t] += u;
        __syncthreads();
    }
    int run = g_part[b] + ts[t] - s;    // exclusive prefix for this thread
#pragma unroll
    for (int k = 0; k < 8; ++k) {
        int g = base + k;
        if (g < NTOT) {
            g_off[g]  = run;
            g_cur[g]  = run;
            g_dinv[g] = rsqrtf((float)(1 + v[k]));
            run += v[k];
        }
    }
}

// ---------------- GCN gather (xw pre-scaled by dinv[src] in GEMM epilogue) --
// out[n] = b + dinv[n] * ( xws[n] + sum_{s in CSR(n)} xws[s] )
__global__ void __launch_bounds__(256) gather_graph(const float* __restrict__ xws,
                                                    const float* __restrict__ bias,
                                                    float* __restrict__ out) {
    int gw = blockIdx.x * 8 + (threadIdx.x >> 5);
    if (gw >= NC * NN) return;
    int lane = threadIdx.x & 31;
    int c = gw / NN;
    int n = gw - c * NN;
    const float* xwc = xws + (size_t)c * NN * 128;
    float4 acc = *(const float4*)(xwc + (size_t)n * 128 + lane * 4);
    int beg = g_off[gw];
    int end = beg + g_cnt[gw];
    int j = beg;
    for (; j + 3 < end; j += 4) {
        int s0 = g_csr[j], s1 = g_csr[j + 1], s2 = g_csr[j + 2], s3 = g_csr[j + 3];
        float4 a0 = *(const float4*)(xwc + (size_t)s0 * 128 + lane * 4);
        float4 a1 = *(const float4*)(xwc + (size_t)s1 * 128 + lane * 4);
        float4 a2 = *(const float4*)(xwc + (size_t)s2 * 128 + lane * 4);
        float4 a3 = *(const float4*)(xwc + (size_t)s3 * 128 + lane * 4);
        acc.x += a0.x + a1.x + a2.x + a3.x;
        acc.y += a0.y + a1.y + a2.y + a3.y;
        acc.z += a0.z + a1.z + a2.z + a3.z;
        acc.w += a0.w + a1.w + a2.w + a3.w;
    }
    for (; j < end; ++j) {
        int s0 = g_csr[j];
        float4 a0 = *(const float4*)(xwc + (size_t)s0 * 128 + lane * 4);
        acc.x += a0.x; acc.y += a0.y; acc.z += a0.z; acc.w += a0.w;
    }
    float dv = g_dinv[gw];
    float4 b4 = *(const float4*)(bias + lane * 4);
    float4 o = make_float4(b4.x + acc.x * dv, b4.y + acc.y * dv,
                           b4.z + acc.z * dv, b4.w + acc.w * dv);
    *(float4*)(out + (size_t)gw * 128 + lane * 4) = o;
}

// ori branch: output row i aggregates node rel[i]; optional relu (fused permute)
__global__ void __launch_bounds__(256) gather_ori(const float* __restrict__ xws,
                                                  const float* __restrict__ bias,
                                                  float* __restrict__ out, int doRelu) {
    int gw = blockIdx.x * 8 + (threadIdx.x >> 5);
    if (gw >= NN) return;
    int lane = threadIdx.x & 31;
    int n = g_rel[gw];
    int fi = NC * NN + n;
    float4 acc = *(const float4*)(xws + (size_t)n * 128 + lane * 4);
    int beg = g_off[fi];
    int end = beg + g_cnt[fi];
    int j = beg;
    for (; j + 3 < end; j += 4) {
        int s0 = g_csr[j], s1 = g_csr[j + 1], s2 = g_csr[j + 2], s3 = g_csr[j + 3];
        float4 a0 = *(const float4*)(xws + (size_t)s0 * 128 + lane * 4);
        float4 a1 = *(const float4*)(xws + (size_t)s1 * 128 + lane * 4);
        float4 a2 = *(const float4*)(xws + (size_t)s2 * 128 + lane * 4);
        float4 a3 = *(const float4*)(xws + (size_t)s3 * 128 + lane * 4);
        acc.x += a0.x + a1.x + a2.x + a3.x;
        acc.y += a0.y + a1.y + a2.y + a3.y;
        acc.z += a0.z + a1.z + a2.z + a3.z;
        acc.w += a0.w + a1.w + a2.w + a3.w;
    }
    for (; j < end; ++j) {
        int s0 = g_csr[j];
        float4 a0 = *(const float4*)(xws + (size_t)s0 * 128 + lane * 4);
        acc.x += a0.x; acc.y += a0.y; acc.z += a0.z; acc.w += a0.w;
    }
    float dv = g_dinv[fi];
    float4 b4 = *(const float4*)(bias + lane * 4);
    float4 o = make_float4(b4.x + acc.x * dv, b4.y + acc.y * dv,
                           b4.z + acc.z * dv, b4.w + acc.w * dv);
    if (doRelu) {
        o.x = fmaxf(o.x, 0.f); o.y = fmaxf(o.y, 0.f);
        o.z = fmaxf(o.z, 0.f); o.w = fmaxf(o.w, 0.f);
    }
    *(float4*)(out + (size_t)gw * 128 + lane * 4) = o;
}

// ---------------- qt[c] = Wk @ (label[c] @ Wq + bq) -------------------------
__global__ void q_kernel(const float* __restrict__ label,
                         const float* __restrict__ Wq,
                         const float* __restrict__ bq,
                         const float* __restrict__ Wk) {
    __shared__ float Ls[NC * 128];
    __shared__ float Qs[NC * 128];
    int t = threadIdx.x;  // 128 threads
    for (int i = t; i < NC * 128; i += 128) Ls[i] = label[i];
    __syncthreads();
    for (int c = 0; c < NC; ++c) {
        float acc = bq[t];
#pragma unroll 8
        for (int h = 0; h < 128; ++h) acc += Ls[c * 128 + h] * Wq[h * 128 + t];
        Qs[c * 128 + t] = acc;
    }
    __syncthreads();
    float acc[NC];
#pragma unroll
    for (int c = 0; c < NC; ++c) acc[c] = 0.f;
    for (int j = 0; j < 128; ++j) {
        float wv = Wk[t * 128 + j];
#pragma unroll
        for (int c = 0; c < NC; ++c) acc[c] += wv * Qs[c * 128 + j];
    }
#pragma unroll
    for (int c = 0; c < NC; ++c) g_qt[c * 128 + t] = acc[c];
}

// ---------------- attention scores + mix: mixed = softmax(qt . feat) @ feat -
__global__ void __launch_bounds__(128) attn_mix(const float* __restrict__ feat,
                                                float* __restrict__ mixed) {
    __shared__ float qt_s[NC][128];
    __shared__ float s_s[4][NC][NC];
    int tid = threadIdx.x;
    for (int i = tid; i < NC * 128; i += 128) qt_s[i >> 7][i & 127] = g_qt[i];
    __syncthreads();
    int w = tid >> 5, lane = tid & 31;
    int n = blockIdx.x * 4 + w;
    if (n >= NN) return;

    float4 fr[NC];
#pragma unroll
    for (int k = 0; k < NC; ++k)
        fr[k] = *(const float4*)(feat + ((size_t)k * NN + n) * 128 + lane * 4);

#pragma unroll
    for (int c = 0; c < NC; ++c) {
        float4 qc = *(const float4*)(&qt_s[c][lane * 4]);
#pragma unroll
        for (int k = 0; k < NC; ++k) {
            float p = qc.x * fr[k].x + qc.y * fr[k].y + qc.z * fr[k].z + qc.w * fr[k].w;
            p += __shfl_xor_sync(0xffffffffu, p, 16);
            p += __shfl_xor_sync(0xffffffffu, p, 8);
            p += __shfl_xor_sync(0xffffffffu, p, 4);
            p += __shfl_xor_sync(0xffffffffu, p, 2);
            p += __shfl_xor_sync(0xffffffffu, p, 1);
            if (lane == 0) s_s[w][c][k] = p;
        }
    }
    __syncwarp();
    const float scale = 0.08838834764831845f;  // 1/sqrt(128)
    if (lane < NC) {
        float m = -1e30f;
#pragma unroll
        for (int k = 0; k < NC; ++k) m = fmaxf(m, s_s[w][lane][k]);
        float e[NC], sum = 0.f;
#pragma unroll
        for (int k = 0; k < NC; ++k) {
            e[k] = expf((s_s[w][lane][k] - m) * scale);
            sum += e[k];
        }
        float inv = 1.f / sum;
#pragma unroll
        for (int k = 0; k < NC; ++k) s_s[w][lane][k] = e[k] * inv;
    }
    __syncwarp();

    float4 acc[NC];
#pragma unroll
    for (int c = 0; c < NC; ++c) acc[c] = make_float4(0.f, 0.f, 0.f, 0.f);
#pragma unroll
    for (int k = 0; k < NC; ++k) {
        float4 vk = fr[k];
#pragma unroll
        for (int c = 0; c < NC; ++c) {
            float sc = s_s[w][c][k];
            acc[c].x += sc * vk.x; acc[c].y += sc * vk.y;
            acc[c].z += sc * vk.z; acc[c].w += sc * vk.w;
        }
    }
#pragma unroll
    for (int c = 0; c < NC; ++c)
        *(float4*)(mixed + ((size_t)c * NN + n) * 128 + lane * 4) = acc[c];
}

// ---------------- ori-branch relative index --------------------------------
__global__ void board_kernel(const int* __restrict__ src_ids) {
    int i = blockIdx.x * blockDim.x + threadIdx.x;
    if (i < NN) g_board[src_ids[i]] = i;
}
__global__ void rel_kernel(const int* __restrict__ dst_ids) {
    int i = blockIdx.x * blockDim.x + threadIdx.x;
    if (i < NN) g_rel[i] = g_board[dst_ids[i]];
}

// ---------------- orchestration --------------------------------------------
extern "C" void kernel_launch(void* const* d_in, const int* in_sizes, int n_in,
                              void* d_out, int out_size) {
    const float* gfe0  = (const float*)d_in[0];
    const float* ofe0  = (const float*)d_in[1];
    const float* label = (const float*)d_in[2];
    const float* Wl[2] = {(const float*)d_in[3], (const float*)d_in[5]};
    const float* bl[2] = {(const float*)d_in[4], (const float*)d_in[6]};
    const float* Wq = (const float*)d_in[7];
    const float* bq = (const float*)d_in[8];
    const float* Wk = (const float*)d_in[9];
    const float* Wv = (const float*)d_in[11];
    const float* bv = (const float*)d_in[12];
    const int* ge      = (const int*)d_in[13];
    const int* oe      = (const int*)d_in[14];
    const int* src_ids = (const int*)d_in[15];
    const int* dst_ids = (const int*)d_in[16];

    float* out_gfe = (float*)d_out;
    float* out_ofe = out_gfe + (size_t)NC * NN * ND;

    float *bufA, *bufB, *mixed, *xw, *oxw, *ofeB, *dinv;
    cudaGetSymbolAddress((void**)&bufA,  g_bufA);
    cudaGetSymbolAddress((void**)&bufB,  g_bufB);
    cudaGetSymbolAddress((void**)&mixed, g_mixed);
    cudaGetSymbolAddress((void**)&xw,    g_xw);
    cudaGetSymbolAddress((void**)&oxw,   g_oxw);
    cudaGetSymbolAddress((void**)&ofeB,  g_ofe);
    cudaGetSymbolAddress((void**)&dinv,  g_dinv);

    cudaFuncSetAttribute(gemm128, cudaFuncAttributeMaxDynamicSharedMemorySize, GEMM_SMEM);

    q_kernel<<<1, 128>>>(label, Wq, bq, Wk);

    const float* cur_g = gfe0;
    const float* cur_o = ofe0;

    const int edgeBlocks = (int)((TE + 255) / 256);

    for (int layer = 0; layer < 2; ++layer) {
        const float* W = Wl[layer];
        const float* b = bl[layer];
        int relu = (layer == 0);

        // ---- merged CSR build: graph (NC) + ori, flat offsets ----
        zero_cnt<<<(NTOT + 255) / 256, 256>>>();
        count_all<<<edgeBlocks, 256>>>(ge, oe, layer);
        scan_p1<<<SCAN_BLOCKS, 256>>>();
        scan_p2<<<1, 512>>>(SCAN_BLOCKS);
        scan_p3<<<SCAN_BLOCKS, 256>>>();
        fill_all<<<edgeBlocks, 256>>>(ge, oe, layer);

        // ---- graph branch ----
        gemm128<<<(NC * NN + 127) / 128, 256, GEMM_SMEM>>>(cur_g, W, nullptr, dinv, xw, NC * NN, 0);
        gather_graph<<<(NC * NN + 7) / 8, 256>>>(xw, b, bufA);

        // ---- attention across classes (K GEMM eliminated; V GEMM moved) ----
        attn_mix<<<(NN + 3) / 4, 128>>>(bufA, mixed);
        float* gout = relu ? bufB : out_gfe;
        gemm128<<<(NC * NN + 127) / 128, 256, GEMM_SMEM>>>(mixed, Wv, bv, nullptr, gout, NC * NN, relu);
        cur_g = bufB;

        // ---- original-graph branch ----
        gemm128<<<(NN + 127) / 128, 256, GEMM_SMEM>>>(cur_o, W, nullptr, dinv + NC * NN, oxw, NN, 0);
        board_kernel<<<(NN + 255) / 256, 256>>>(src_ids + (size_t)layer * NN);
        rel_kernel<<<(NN + 255) / 256, 256>>>(dst_ids + (size_t)layer * NN);
        float* oout = relu ? ofeB : out_ofe;
        gather_ori<<<(NN + 7) / 8, 256>>>(oxw, b, oout, relu);
        cur_o = ofeB;
    }
}